// round 2
// baseline (speedup 1.0000x reference)
#include <cuda_runtime.h>

// ---------------- problem constants ----------------
#define BQ 2
#define TQ 8
#define YQ 128
#define XQ 128
#define CIN 128
#define COUTQ 64
#define YOQ 255
#define XOQ 255
#define NPTS 262144
#define NCELL (BQ*TQ*YQ*XQ)          // 262144 input cells
#define NSITE (BQ*TQ*YOQ*XOQ)        // 1040400 output sites
#define EPSQ 1e-5f

// ---------------- device scratch (no allocs allowed) ----------------
__device__ __align__(16) float g_A[(size_t)NCELL * CIN];   // dense cell features [cell][ci], 134MB
__device__ __align__(16) int   g_occ[NCELL];               // points per cell
__device__ unsigned char      g_mask[NSITE];               // active output sites
__device__ __align__(16) float g_sum[COUTQ];
__device__ __align__(16) float g_sumsq[COUTQ];
__device__ int                g_nactive;
__device__ __align__(16) float g_scale[COUTQ];
__device__ __align__(16) float g_shift[COUTQ];

// ---------------- K0: zero scratch ----------------
__global__ void k_zero() {
    int idx = blockIdx.x * 256 + threadIdx.x;            // grid = 32768 blocks
    if (idx < NCELL * CIN / 4)
        ((float4*)g_A)[idx] = make_float4(0.f, 0.f, 0.f, 0.f);
    if (idx < NCELL / 4)
        ((int4*)g_occ)[idx] = make_int4(0, 0, 0, 0);
    if (idx < COUTQ) { g_sum[idx] = 0.f; g_sumsq[idx] = 0.f; }
    if (idx == 0) g_nactive = 0;
}

// ---------------- K1: scatter points into dense cell grid ----------------
__global__ void k_scatter(const float* __restrict__ feats,
                          const int* __restrict__ cb, const int* __restrict__ ct,
                          const int* __restrict__ cy, const int* __restrict__ cx) {
    int i = blockIdx.x * 256 + threadIdx.x;              // grid = NPTS*32/256 blocks
    if (i >= NPTS * 32) return;
    int p  = i >> 5;                                     // point
    int c4 = i & 31;                                     // float4 group of channels
    int cell = ((cb[p] * TQ + ct[p]) * YQ + cy[p]) * XQ + cx[p];
    float4 v = ((const float4*)feats)[p * 32 + c4];
    float* dst = &g_A[(size_t)cell * CIN + c4 * 4];
    atomicAdd(dst + 0, v.x);
    atomicAdd(dst + 1, v.y);
    atomicAdd(dst + 2, v.z);
    atomicAdd(dst + 3, v.w);
    if (c4 == 0) atomicAdd(&g_occ[cell], 1);
}

// ---------------- K2: gather transposed conv + BN stats + mask ----------------
__device__ __forceinline__ void gemm_chunk(float (&acc)[2][4],
                                           const float* __restrict__ r0,
                                           const float* __restrict__ r1,
                                           const float* __restrict__ Ws, int cog) {
#pragma unroll 16
    for (int ci = 0; ci < 64; ci++) {
        float a0 = r0[ci], a1 = r1[ci];
        float4 w = *(const float4*)(Ws + ci * COUTQ + cog * 4);
        acc[0][0] += a0 * w.x; acc[0][1] += a0 * w.y;
        acc[0][2] += a0 * w.z; acc[0][3] += a0 * w.w;
        acc[1][0] += a1 * w.x; acc[1][1] += a1 * w.y;
        acc[1][2] += a1 * w.z; acc[1][3] += a1 * w.w;
    }
}

__global__ void __launch_bounds__(256) k_conv(const float* __restrict__ W,
                                              float* __restrict__ out) {
    __shared__ float As[33][CIN];        // A slab: 33 cells x 128 ci (16.9KB)
    __shared__ float Ws[64 * COUTQ];     // W chunk: 64 ci x 64 co (16KB)
    __shared__ float red[8][16][8];      // stats reduce (4KB)

    const int tid = threadIdx.x;
    const int cog = tid & 15;            // 4-cout group
    const int sg  = tid >> 4;            // 0..15 site-pair group
    const int ox0 = blockIdx.x * 64;
    const int oy  = blockIdx.y;
    const int bt  = blockIdx.z;
    const int b   = bt >> 3;
    const int ot  = bt & 7;
    const int cxb = ox0 >> 1;

    float aE[2][4] = {{0.f,0.f,0.f,0.f},{0.f,0.f,0.f,0.f}};
    float aO[2][4] = {{0.f,0.f,0.f,0.f},{0.f,0.f,0.f,0.f}};

    // y taps for this output row (parity decides ky set)
    int nky, cys[2], kys[2];
    if ((oy & 1) == 0) { nky = 1; cys[0] = oy >> 1;       kys[0] = 1; }
    else               { nky = 2; cys[0] = (oy + 1) >> 1; kys[0] = 0;
                                  cys[1] = (oy - 1) >> 1; kys[1] = 2; }

    for (int kt = 0; kt < 3; kt++) {
        int ctv = ot + 1 - kt;
        if (ctv < 0 || ctv >= TQ) continue;
        for (int yt = 0; yt < nky; yt++) {
            int cy = cys[yt], kyw = kys[yt];
            int cellbase = ((b * TQ + ctv) * YQ + cy) * XQ;
            __syncthreads();                        // prior GEMM reads of As done
            // load slab: 33 cells x 32 float4
            for (int i = tid; i < 33 * 32; i += 256) {
                int cell = i >> 5, c4 = i & 31;
                int cx = cxb + cell;
                float4 v = (cx < XQ)
                    ? ((const float4*)g_A)[(size_t)(cellbase + cx) * 32 + c4]
                    : make_float4(0.f, 0.f, 0.f, 0.f);
                *(float4*)&As[cell][c4 * 4] = v;
            }
            for (int kxi = 0; kxi < 3; kxi++) {
                int kx, soff;
                if (kxi == 0)      { kx = 1; soff = 0; }   // even ox sites
                else if (kxi == 1) { kx = 0; soff = 1; }   // odd ox sites
                else               { kx = 2; soff = 0; }   // odd ox sites
                const float* Wm = W + (size_t)(((kt * 3 + kyw) * 3 + kx) * CIN) * COUTQ;
                for (int ch = 0; ch < 2; ch++) {
                    __syncthreads();                // prior reads of Ws (and As stores on 1st)
                    const float* Wsrc = Wm + ch * 64 * COUTQ;
                    for (int i = tid; i < 1024; i += 256)
                        ((float4*)Ws)[i] = ((const float4*)Wsrc)[i];
                    __syncthreads();
                    const float* r0 = &As[2 * sg + soff][ch * 64];
                    const float* r1 = &As[2 * sg + 1 + soff][ch * 64];
                    if (kxi == 0) gemm_chunk(aE, r0, r1, Ws, cog);
                    else          gemm_chunk(aO, r0, r1, Ws, cog);
                }
            }
        }
    }

    // ---- write raw conv output + accumulate BN stats ----
    const int sbase = ((b * TQ + ot) * YOQ + oy) * XOQ;
    float s[4] = {0.f,0.f,0.f,0.f}, q[4] = {0.f,0.f,0.f,0.f};
#pragma unroll
    for (int jj = 0; jj < 2; jj++) {
        int j   = 2 * sg + jj;
        int oxE = ox0 + 2 * j;
        int oxO = oxE + 1;
        // even site always valid (max ox = 254)
        ((float4*)out)[(size_t)(sbase + oxE) * 16 + cog] =
            make_float4(aE[jj][0], aE[jj][1], aE[jj][2], aE[jj][3]);
#pragma unroll
        for (int k = 0; k < 4; k++) { s[k] += aE[jj][k]; q[k] += aE[jj][k] * aE[jj][k]; }
        if (oxO < XOQ) {
            ((float4*)out)[(size_t)(sbase + oxO) * 16 + cog] =
                make_float4(aO[jj][0], aO[jj][1], aO[jj][2], aO[jj][3]);
#pragma unroll
            for (int k = 0; k < 4; k++) { s[k] += aO[jj][k]; q[k] += aO[jj][k] * aO[jj][k]; }
        }
    }
    // reduce within warp: lane i and i^16 share cog
#pragma unroll
    for (int k = 0; k < 4; k++) {
        s[k] += __shfl_xor_sync(0xffffffffu, s[k], 16);
        q[k] += __shfl_xor_sync(0xffffffffu, q[k], 16);
    }
    const int w = tid >> 5, lane = tid & 31;
    __syncthreads();
    if (lane < 16) {
#pragma unroll
        for (int k = 0; k < 4; k++) { red[w][lane][k] = s[k]; red[w][lane][4 + k] = q[k]; }
    }
    __syncthreads();
    if (tid < COUTQ) {
        float S = 0.f, Q = 0.f;
        int cg = tid >> 2, k = tid & 3;
#pragma unroll
        for (int ww = 0; ww < 8; ww++) { S += red[ww][cg][k]; Q += red[ww][cg][4 + k]; }
        atomicAdd(&g_sum[tid], S);
        atomicAdd(&g_sumsq[tid], Q);
    }

    // ---- active-site mask (one thread per site) ----
    bool act = false;
    if (tid < 64) {
        int ox = ox0 + tid;
        if (ox < XOQ) {
            int xc[2], nxc = 0;
            if ((ox & 1) == 0) { xc[nxc++] = ox >> 1; }
            else {
                int c0 = (ox + 1) >> 1;
                if (c0 < XQ) xc[nxc++] = c0;
                xc[nxc++] = (ox - 1) >> 1;
            }
            for (int kt = 0; kt < 3 && !act; kt++) {
                int ctv = ot + 1 - kt;
                if (ctv < 0 || ctv >= TQ) continue;
                for (int yt = 0; yt < nky && !act; yt++) {
                    int cb2 = ((b * TQ + ctv) * YQ + cys[yt]) * XQ;
                    for (int xi = 0; xi < nxc; xi++)
                        if (g_occ[cb2 + xc[xi]] > 0) { act = true; break; }
                }
            }
            g_mask[sbase + ox] = act ? 1 : 0;
        }
    }
    unsigned bal = __ballot_sync(0xffffffffu, act);
    if (tid < 64 && lane == 0) atomicAdd(&g_nactive, __popc(bal));
}

// ---------------- K3: fold BN params ----------------
__global__ void k_bn(const float* __restrict__ gamma, const float* __restrict__ beta) {
    int c = threadIdx.x;
    if (c >= COUTQ) return;
    float n = (float)max(g_nactive, 1);
    float mean = g_sum[c] / n;
    float var  = g_sumsq[c] / n - mean * mean;
    float rstd = rsqrtf(var + EPSQ);
    float sc   = rstd * gamma[c];
    g_scale[c] = sc;
    g_shift[c] = beta[c] - mean * sc;
}

// ---------------- K4: normalize + relu + mask (in place) ----------------
__global__ void k_final(float* __restrict__ out) {
    int i = blockIdx.x * 256 + threadIdx.x;              // grid = NSITE*16/256 = 65025
    int site = i >> 4;
    int cg   = i & 15;
    float4 v  = ((float4*)out)[i];
    float4 sc = ((const float4*)g_scale)[cg];
    float4 sh = ((const float4*)g_shift)[cg];
    float  m  = g_mask[site] ? 1.f : 0.f;
    v.x = fmaxf(v.x * sc.x + sh.x, 0.f) * m;
    v.y = fmaxf(v.y * sc.y + sh.y, 0.f) * m;
    v.z = fmaxf(v.z * sc.z + sh.z, 0.f) * m;
    v.w = fmaxf(v.w * sc.w + sh.w, 0.f) * m;
    ((float4*)out)[i] = v;
}

// ---------------- launch ----------------
extern "C" void kernel_launch(void* const* d_in, const int* in_sizes, int n_in,
                              void* d_out, int out_size) {
    const float* feats  = (const float*)d_in[0];
    const float* weight = (const float*)d_in[1];
    const float* gamma  = (const float*)d_in[2];
    const float* beta   = (const float*)d_in[3];
    const int*   cb     = (const int*)d_in[4];
    const int*   ct     = (const int*)d_in[5];
    const int*   cy     = (const int*)d_in[6];
    const int*   cx     = (const int*)d_in[7];
    float* out = (float*)d_out;

    k_zero<<<NCELL * CIN / 4 / 256, 256>>>();
    k_scatter<<<NPTS * 32 / 256, 256>>>(feats, cb, ct, cy, cx);
    dim3 cgrid(4, YOQ, BQ * TQ);
    k_conv<<<cgrid, 256>>>(weight, out);
    k_bn<<<1, 64>>>(gamma, beta);
    k_final<<<NSITE * 16 / 256, 256>>>(out);
}

// round 4
// speedup vs baseline: 2.1711x; 2.1711x over previous
#include <cuda_runtime.h>
#include <cuda_bf16.h>
#include <cstdint>

// ---------------- problem constants ----------------
#define BQ 2
#define TQ 8
#define YQ 128
#define XQ 128
#define CIN 128
#define COUTQ 64
#define YOQ 255
#define XOQ 255
#define NPTS 262144
#define NCELL (BQ*TQ*YQ*XQ)
#define NSITE (BQ*TQ*YOQ*XOQ)
#define EPSQ 1e-5f

// ---------------- device scratch ----------------
__device__ __align__(16) float g_A[(size_t)NCELL * CIN];   // dense cell features
__device__ __align__(16) int   g_occ[NCELL];
__device__ unsigned char       g_mask[NSITE];
__device__ __align__(16) float g_sum[COUTQ];
__device__ __align__(16) float g_sumsq[COUTQ];
__device__ int                 g_nactive;
__device__ __align__(16) float g_scale[COUTQ];
__device__ __align__(16) float g_shift[COUTQ];
// pre-split, pre-swizzled bf16 weight images: [27 koff][hi(16KB), lo(16KB)]
__device__ __align__(16) unsigned char g_Wt[27 * 2 * 16384];

// ---------------- helpers ----------------
__device__ __forceinline__ uint32_t smem_u32(const void* p) {
    uint32_t a;
    asm("{ .reg .u64 t; cvta.to.shared.u64 t, %1; cvt.u32.u64 %0, t; }" : "=r"(a) : "l"(p));
    return a;
}
__device__ __forceinline__ void ldsm4(uint32_t* r, uint32_t addr) {
    asm volatile("ldmatrix.sync.aligned.m8n8.x4.shared.b16 {%0,%1,%2,%3}, [%4];"
        : "=r"(r[0]), "=r"(r[1]), "=r"(r[2]), "=r"(r[3]) : "r"(addr));
}
__device__ __forceinline__ void mma16816(float* c, const uint32_t* a, uint32_t b0, uint32_t b1) {
    asm volatile("mma.sync.aligned.m16n8k16.row.col.f32.bf16.bf16.f32 "
        "{%0,%1,%2,%3}, {%4,%5,%6,%7}, {%8,%9}, {%0,%1,%2,%3};"
        : "+f"(c[0]), "+f"(c[1]), "+f"(c[2]), "+f"(c[3])
        : "r"(a[0]), "r"(a[1]), "r"(a[2]), "r"(a[3]), "r"(b0), "r"(b1));
}
// Row-major tile (row, 256B of k) with XOR-swizzled 16B chunks.
// chunk c16 (0..15): phys byte off = ((c16&8)<<4) | (((c16&7)^(row&7))<<4)
__device__ __forceinline__ uint32_t chunk_off(int c16, int rs) {
    return (uint32_t)(((c16 & 8) << 4) | (((c16 & 7) ^ rs) << 4));
}

// ---------------- K0: zero scratch ----------------
__global__ void k_zero() {
    int idx = blockIdx.x * 256 + threadIdx.x;
    if (idx < NCELL * CIN / 4)
        ((float4*)g_A)[idx] = make_float4(0.f, 0.f, 0.f, 0.f);
    if (idx < NCELL / 4)
        ((int4*)g_occ)[idx] = make_int4(0, 0, 0, 0);
    if (idx < COUTQ) { g_sum[idx] = 0.f; g_sumsq[idx] = 0.f; }
    if (idx == 0) g_nactive = 0;
}

// ---------------- K0b: split+swizzle weights ----------------
// W src layout [koff][ci][co]; image layout: row=co (64 rows x 256B), k=ci bf16
__global__ void k_prepw(const float* __restrict__ W) {
    int i = blockIdx.x * 256 + threadIdx.x;
    if (i >= 27 * CIN * COUTQ) return;
    int koff = i / (CIN * COUTQ);
    int r    = i % (CIN * COUTQ);
    int ci = r / COUTQ, co = r % COUTQ;
    float x = W[i];
    __nv_bfloat16 h = __float2bfloat16_rn(x);
    __nv_bfloat16 l = __float2bfloat16_rn(x - __bfloat162float(h));
    int c16 = ci >> 3;
    uint32_t off = (uint32_t)(co * 256) + chunk_off(c16, co & 7) + (ci & 7) * 2;
    *(__nv_bfloat16*)(g_Wt + (size_t)koff * 32768 + off)         = h;
    *(__nv_bfloat16*)(g_Wt + (size_t)koff * 32768 + 16384 + off) = l;
}

// ---------------- K1: scatter points ----------------
__global__ void k_scatter(const float* __restrict__ feats,
                          const int* __restrict__ cb, const int* __restrict__ ct,
                          const int* __restrict__ cy, const int* __restrict__ cx) {
    int i = blockIdx.x * 256 + threadIdx.x;
    if (i >= NPTS * 32) return;
    int p  = i >> 5;
    int c4 = i & 31;
    int cell = ((cb[p] * TQ + ct[p]) * YQ + cy[p]) * XQ + cx[p];
    float4 v = ((const float4*)feats)[p * 32 + c4];
    float* dst = &g_A[(size_t)cell * CIN + c4 * 4];
    atomicAdd(dst + 0, v.x);
    atomicAdd(dst + 1, v.y);
    atomicAdd(dst + 2, v.z);
    atomicAdd(dst + 3, v.w);
    if (c4 == 0) atomicAdd(&g_occ[cell], 1);
}

// ---------------- K2: mma.sync gather transposed conv + BN stats + mask ----------------
// smem: A parts at [0,32768) hi, [32768,65536) lo  (rows = cells 0..127)
//       W at 65536 + kx*32768 + part*16384 (rows = couts 0..63)
// epilogue stats reduce reuses W region.
#define SM_W 65536
#define CONV_DYN_SMEM (65536 + 3*32768)

__global__ void __launch_bounds__(256, 1) k_conv(float* __restrict__ out) {
    extern __shared__ char smem[];
    const uint32_t sb = smem_u32(smem);
    const int tid = threadIdx.x, wid = tid >> 5, lane = tid & 31;

    const int bid = blockIdx.x;
    const int oy = bid % YOQ;
    const int bt = bid / YOQ;
    const int b = bt >> 3, ot = bt & 7;

    // y taps
    int nky, cys[2], kys[2];
    if ((oy & 1) == 0) { nky = 1; cys[0] = oy >> 1;       kys[0] = 1; }
    else               { nky = 2; cys[0] = (oy + 1) >> 1; kys[0] = 0;
                                  cys[1] = (oy - 1) >> 1; kys[1] = 2; }

    // per-thread ldmatrix geometry
    const int r0   = wid << 4;                 // warp's 16-row tile base
    const int matL = lane >> 3, rr = lane & 7;
    // A: a-frag rows
    const int rA0 = r0 + rr + ((matL & 1) << 3);
    const int rA1 = rA0 + 1;                   // kx=0 shifted rows (row 128 reads junk smem; masked out)
    const int cA  = matL >> 1;
    const uint32_t baseA0 = (uint32_t)rA0 * 256; const int rs0 = rA0 & 7;
    const uint32_t baseA1 = (uint32_t)rA1 * 256; const int rs1 = rA1 & 7;
    // B: n rows
    const int nr  = rr + ((matL >> 1) << 3);
    const int cB  = matL & 1;
    const uint32_t baseB = (uint32_t)nr * 256; const int rsB = nr & 7;

    float accE[8][4], accO[8][4];
#pragma unroll
    for (int i = 0; i < 8; i++)
#pragma unroll
        for (int j = 0; j < 4; j++) { accE[i][j] = 0.f; accO[i][j] = 0.f; }

    for (int kt = 0; kt < 3; kt++) {
        int ctv = ot + 1 - kt;
        if (ctv < 0 || ctv >= TQ) continue;
        for (int yt = 0; yt < nky; yt++) {
            int cy = cys[yt], kyw = kys[yt];
            __syncthreads();   // protect smem from prior iteration's readers
            // ---- load + split A slab (128 cells x 128 ci) ----
            const float* src = g_A + (size_t)(((b * TQ + ctv) * YQ + cy) * XQ) * CIN;
            for (int i = tid; i < 2048; i += 256) {
                int cell = i >> 4, c16 = i & 15;
                const float4* p = (const float4*)(src + cell * CIN + c16 * 8);
                float4 v0 = p[0], v1 = p[1];
                float xs[8] = {v0.x, v0.y, v0.z, v0.w, v1.x, v1.y, v1.z, v1.w};
                uint32_t hi4[4], lo4[4];
#pragma unroll
                for (int j = 0; j < 4; j++) {
                    __nv_bfloat16 h0 = __float2bfloat16_rn(xs[2*j]);
                    __nv_bfloat16 h1 = __float2bfloat16_rn(xs[2*j+1]);
                    __nv_bfloat16 l0 = __float2bfloat16_rn(xs[2*j]   - __bfloat162float(h0));
                    __nv_bfloat16 l1 = __float2bfloat16_rn(xs[2*j+1] - __bfloat162float(h1));
                    hi4[j] = ((uint32_t)__bfloat16_as_ushort(h1) << 16) | __bfloat16_as_ushort(h0);
                    lo4[j] = ((uint32_t)__bfloat16_as_ushort(l1) << 16) | __bfloat16_as_ushort(l0);
                }
                uint32_t off = (uint32_t)(cell * 256) + chunk_off(c16, cell & 7);
                *(uint4*)(smem + off)         = make_uint4(hi4[0], hi4[1], hi4[2], hi4[3]);
                *(uint4*)(smem + 32768 + off) = make_uint4(lo4[0], lo4[1], lo4[2], lo4[3]);
            }
            // ---- copy W images for kx=0,1,2 (hi+lo) ----
            int koff0 = (kt * 3 + kyw) * 3;
            for (int i = tid; i < 6 * 1024; i += 256) {
                int blk = i >> 10, within = i & 1023;
                int kxb = blk >> 1, part = blk & 1;
                const uint4* s4 = (const uint4*)(g_Wt + ((size_t)(koff0 + kxb) * 2 + part) * 16384);
                uint4* d4 = (uint4*)(smem + SM_W + kxb * 32768 + part * 16384);
                d4[within] = s4[within];
            }
            __syncthreads();
            // ---- 3 split passes: (Ahi,Whi) (Ahi,Wlo) (Alo,Whi) ----
#pragma unroll
            for (int pass = 0; pass < 3; pass++) {
                const uint32_t Ab = sb + ((pass == 2) ? 32768u : 0u);
                const uint32_t wp = (pass == 1) ? 16384u : 0u;
                const uint32_t W0 = sb + SM_W + 0 * 32768 + wp;
                const uint32_t W1 = sb + SM_W + 1 * 32768 + wp;
                const uint32_t W2 = sb + SM_W + 2 * 32768 + wp;
#pragma unroll
                for (int s = 0; s < 8; s++) {
                    int c16a = 2 * s + cA;
                    int c16b = 2 * s + cB;
                    uint32_t offA0 = chunk_off(c16a, rs0);
                    uint32_t offA1 = chunk_off(c16a, rs1);
                    uint32_t offB  = chunk_off(c16b, rsB);
                    uint32_t a0[4], a1[4];
                    ldsm4(a0, Ab + baseA0 + offA0);
                    ldsm4(a1, Ab + baseA1 + offA1);
                    uint32_t b0f[16], b1f[16], b2f[16];
#pragma unroll
                    for (int p2 = 0; p2 < 4; p2++) {
                        uint32_t ro = baseB + (uint32_t)(p2 * 4096) + offB;
                        ldsm4(&b1f[4 * p2], W1 + ro);
                        ldsm4(&b2f[4 * p2], W2 + ro);
                        ldsm4(&b0f[4 * p2], W0 + ro);
                    }
#pragma unroll
                    for (int nt = 0; nt < 8; nt++) {
                        int i2 = ((nt >> 1) << 2) + ((nt & 1) << 1);
                        mma16816(accE[nt], a0, b1f[i2], b1f[i2 + 1]);  // even: kx=1, cell m
                        mma16816(accO[nt], a0, b2f[i2], b2f[i2 + 1]);  // odd:  kx=2, cell m
                        mma16816(accO[nt], a1, b0f[i2], b0f[i2 + 1]);  // odd:  kx=0, cell m+1
                    }
                }
            }
        }
    }

    // ---------------- epilogue: stores + stats ----------------
    const int g = lane >> 2;
    const int n0base = (lane & 3) * 2;
    const int sbase = ((b * TQ + ot) * YOQ + oy) * XOQ;
    const int mA = r0 + g;        // rows for c0,c1
    const int mB = r0 + g + 8;    // rows for c2,c3
    const bool oddBvalid = (mB != 127);   // odd site ox=255 doesn't exist

    float sl[16], ql[16];
#pragma unroll
    for (int nt = 0; nt < 8; nt++) {
        int n0 = nt * 8 + n0base;
        // even sites
        *(float2*)(out + (size_t)(sbase + 2 * mA) * COUTQ + n0) =
            make_float2(accE[nt][0], accE[nt][1]);
        *(float2*)(out + (size_t)(sbase + 2 * mB) * COUTQ + n0) =
            make_float2(accE[nt][2], accE[nt][3]);
        // odd sites
        *(float2*)(out + (size_t)(sbase + 2 * mA + 1) * COUTQ + n0) =
            make_float2(accO[nt][0], accO[nt][1]);
        if (oddBvalid)
            *(float2*)(out + (size_t)(sbase + 2 * mB + 1) * COUTQ + n0) =
                make_float2(accO[nt][2], accO[nt][3]);
#pragma unroll
        for (int c = 0; c < 2; c++) {
            float e0 = accE[nt][c], e2 = accE[nt][2 + c];
            float o0 = accO[nt][c], o2 = oddBvalid ? accO[nt][2 + c] : 0.f;
            sl[nt * 2 + c] = e0 + e2 + o0 + o2;
            ql[nt * 2 + c] = e0 * e0 + e2 * e2 + o0 * o0 + o2 * o2;
        }
    }
    // reduce over g (lanes differing in bits 2..4 share cout set)
#pragma unroll
    for (int d = 4; d <= 16; d <<= 1) {
#pragma unroll
        for (int i = 0; i < 16; i++) {
            sl[i] += __shfl_xor_sync(0xffffffffu, sl[i], d);
            ql[i] += __shfl_xor_sync(0xffffffffu, ql[i], d);
        }
    }
    __syncthreads();                    // all MMAs done; reuse W smem for reduce
    float* redS = (float*)(smem + SM_W);            // [8 warps][4 lanes][16]
    float* redQ = (float*)(smem + SM_W + 8 * 4 * 16 * 4);
    if (lane < 4) {
#pragma unroll
        for (int i = 0; i < 16; i++) {
            redS[(wid * 4 + lane) * 16 + i] = sl[i];
            redQ[(wid * 4 + lane) * 16 + i] = ql[i];
        }
    }
    __syncthreads();
    if (tid < COUTQ) {
        // cout = nt*8 + c4*2 + cc  -> nt = tid>>3, c4 = (tid&7)>>1, cc = tid&1
        int nt = tid >> 3, c4 = (tid & 7) >> 1, cc = tid & 1;
        int idx = nt * 2 + cc;
        float S = 0.f, Q = 0.f;
#pragma unroll
        for (int w2 = 0; w2 < 8; w2++) {
            S += redS[(w2 * 4 + c4) * 16 + idx];
            Q += redQ[(w2 * 4 + c4) * 16 + idx];
        }
        atomicAdd(&g_sum[tid], S);
        atomicAdd(&g_sumsq[tid], Q);
    }

    // ---------------- active-site mask ----------------
    bool act = false;
    if (tid < XOQ) {
        int ox2 = tid;
        int xc[2]; int nxc = 0;
        if ((ox2 & 1) == 0) { xc[nxc++] = ox2 >> 1; }
        else {
            int c0 = (ox2 + 1) >> 1;
            if (c0 < XQ) xc[nxc++] = c0;
            xc[nxc++] = (ox2 - 1) >> 1;
        }
        for (int kt = 0; kt < 3 && !act; kt++) {
            int ctv = ot + 1 - kt;
            if (ctv < 0 || ctv >= TQ) continue;
            for (int yt = 0; yt < nky && !act; yt++) {
                int cb2 = ((b * TQ + ctv) * YQ + cys[yt]) * XQ;
                for (int xi = 0; xi < nxc; xi++)
                    if (g_occ[cb2 + xc[xi]] > 0) { act = true; break; }
            }
        }
        g_mask[sbase + ox2] = act ? 1 : 0;
    }
    unsigned bal = __ballot_sync(0xffffffffu, act);
    if (lane == 0 && bal) atomicAdd(&g_nactive, __popc(bal));
}

// ---------------- K3: fold BN params ----------------
__global__ void k_bn(const float* __restrict__ gamma, const float* __restrict__ beta) {
    int c = threadIdx.x;
    if (c >= COUTQ) return;
    float n = (float)max(g_nactive, 1);
    float mean = g_sum[c] / n;
    float var  = g_sumsq[c] / n - mean * mean;
    float rstd = rsqrtf(var + EPSQ);
    float sc   = rstd * gamma[c];
    g_scale[c] = sc;
    g_shift[c] = beta[c] - mean * sc;
}

// ---------------- K4: normalize + relu + mask (in place) ----------------
__global__ void k_final(float* __restrict__ out) {
    int i = blockIdx.x * 256 + threadIdx.x;
    int site = i >> 4;
    int cg   = i & 15;
    float4 v  = ((float4*)out)[i];
    float4 sc = ((const float4*)g_scale)[cg];
    float4 sh = ((const float4*)g_shift)[cg];
    float  m  = g_mask[site] ? 1.f : 0.f;
    v.x = fmaxf(v.x * sc.x + sh.x, 0.f) * m;
    v.y = fmaxf(v.y * sc.y + sh.y, 0.f) * m;
    v.z = fmaxf(v.z * sc.z + sh.z, 0.f) * m;
    v.w = fmaxf(v.w * sc.w + sh.w, 0.f) * m;
    ((float4*)out)[i] = v;
}

// ---------------- launch ----------------
extern "C" void kernel_launch(void* const* d_in, const int* in_sizes, int n_in,
                              void* d_out, int out_size) {
    const float* feats  = (const float*)d_in[0];
    const float* weight = (const float*)d_in[1];
    const float* gamma  = (const float*)d_in[2];
    const float* beta   = (const float*)d_in[3];
    const int*   cb     = (const int*)d_in[4];
    const int*   ct     = (const int*)d_in[5];
    const int*   cy     = (const int*)d_in[6];
    const int*   cx     = (const int*)d_in[7];
    float* out = (float*)d_out;

    cudaFuncSetAttribute(k_conv, cudaFuncAttributeMaxDynamicSharedMemorySize, CONV_DYN_SMEM);

    k_zero<<<NCELL * CIN / 4 / 256, 256>>>();
    k_prepw<<<(27 * CIN * COUTQ + 255) / 256, 256>>>(weight);
    k_scatter<<<NPTS * 32 / 256, 256>>>(feats, cb, ct, cy, cx);
    k_conv<<<BQ * TQ * YOQ, 256, CONV_DYN_SMEM>>>(out);
    k_bn<<<1, 64>>>(gamma, beta);
    k_final<<<NSITE * 16 / 256, 256>>>(out);
}

// round 5
// speedup vs baseline: 2.2400x; 1.0317x over previous
#include <cuda_runtime.h>
#include <cuda_bf16.h>
#include <cstdint>

// ---------------- problem constants ----------------
#define BQ 2
#define TQ 8
#define YQ 128
#define XQ 128
#define CIN 128
#define COUTQ 64
#define YOQ 255
#define XOQ 255
#define NPTS 262144
#define NCELL (BQ*TQ*YQ*XQ)
#define NSITE (BQ*TQ*YOQ*XOQ)
#define NSLAB (BQ*TQ*YQ)             // 2048 row-slabs of 128 cells
#define EPSQ 1e-5f

// ---------------- device scratch ----------------
__device__ __align__(16) float g_A[(size_t)NCELL * CIN];                 // fp32 cell grid
__device__ __align__(16) unsigned char g_Ab[(size_t)NSLAB * 65536];      // bf16 hi/lo swizzled slab images
__device__ __align__(16) int   g_occ[NCELL];
__device__ unsigned char       g_mask[NSITE];
__device__ __align__(16) float g_sum[COUTQ];
__device__ __align__(16) float g_sumsq[COUTQ];
__device__ int                 g_nactive;
__device__ __align__(16) float g_scale[COUTQ];
__device__ __align__(16) float g_shift[COUTQ];
// pre-split, pre-swizzled bf16 weight images: [27 koff][hi 16KB][lo 16KB]
__device__ __align__(16) unsigned char g_Wt[27 * 2 * 16384];

// ---------------- helpers ----------------
__device__ __forceinline__ uint32_t smem_u32(const void* p) {
    uint32_t a;
    asm("{ .reg .u64 t; cvta.to.shared.u64 t, %1; cvt.u32.u64 %0, t; }" : "=r"(a) : "l"(p));
    return a;
}
__device__ __forceinline__ void ldsm4(uint32_t* r, uint32_t addr) {
    asm volatile("ldmatrix.sync.aligned.m8n8.x4.shared.b16 {%0,%1,%2,%3}, [%4];"
        : "=r"(r[0]), "=r"(r[1]), "=r"(r[2]), "=r"(r[3]) : "r"(addr));
}
__device__ __forceinline__ void mma16816(float* c, const uint32_t* a, uint32_t b0, uint32_t b1) {
    asm volatile("mma.sync.aligned.m16n8k16.row.col.f32.bf16.bf16.f32 "
        "{%0,%1,%2,%3}, {%4,%5,%6,%7}, {%8,%9}, {%0,%1,%2,%3};"
        : "+f"(c[0]), "+f"(c[1]), "+f"(c[2]), "+f"(c[3])
        : "r"(a[0]), "r"(a[1]), "r"(a[2]), "r"(a[3]), "r"(b0), "r"(b1));
}
#define CPASYNC16(sa, gp) \
    asm volatile("cp.async.cg.shared.global [%0], [%1], 16;" :: "r"(sa), "l"(gp))
#define CPCOMMIT() asm volatile("cp.async.commit_group;" ::: "memory")
#define CPWAIT1() asm volatile("cp.async.wait_group 1;" ::: "memory")
#define CPWAIT0() asm volatile("cp.async.wait_group 0;" ::: "memory")

// Row-major tile (row, 256B of k), XOR-swizzled 16B chunks.
__device__ __forceinline__ uint32_t chunk_off(int c16, int rs) {
    return (uint32_t)(((c16 & 8) << 4) | (((c16 & 7) ^ rs) << 4));
}

// ---------------- K0: zero scratch ----------------
__global__ void k_zero() {
    int idx = blockIdx.x * 256 + threadIdx.x;
    if (idx < NCELL * CIN / 4)
        ((float4*)g_A)[idx] = make_float4(0.f, 0.f, 0.f, 0.f);
    if (idx < NCELL / 4)
        ((int4*)g_occ)[idx] = make_int4(0, 0, 0, 0);
    if (idx < COUTQ) { g_sum[idx] = 0.f; g_sumsq[idx] = 0.f; }
    if (idx == 0) g_nactive = 0;
}

// ---------------- K0b: split+swizzle weights ----------------
__global__ void k_prepw(const float* __restrict__ W) {
    int i = blockIdx.x * 256 + threadIdx.x;
    if (i >= 27 * CIN * COUTQ) return;
    int koff = i / (CIN * COUTQ);
    int r    = i % (CIN * COUTQ);
    int ci = r / COUTQ, co = r % COUTQ;
    float x = W[i];
    __nv_bfloat16 h = __float2bfloat16_rn(x);
    __nv_bfloat16 l = __float2bfloat16_rn(x - __bfloat162float(h));
    int c16 = ci >> 3;
    uint32_t off = (uint32_t)(co * 256) + chunk_off(c16, co & 7) + (ci & 7) * 2;
    *(__nv_bfloat16*)(g_Wt + (size_t)koff * 32768 + off)         = h;
    *(__nv_bfloat16*)(g_Wt + (size_t)koff * 32768 + 16384 + off) = l;
}

// ---------------- K1: scatter points ----------------
__global__ void k_scatter(const float* __restrict__ feats,
                          const int* __restrict__ cb, const int* __restrict__ ct,
                          const int* __restrict__ cy, const int* __restrict__ cx) {
    int i = blockIdx.x * 256 + threadIdx.x;
    if (i >= NPTS * 32) return;
    int p  = i >> 5;
    int c4 = i & 31;
    int cell = ((cb[p] * TQ + ct[p]) * YQ + cy[p]) * XQ + cx[p];
    float4 v = ((const float4*)feats)[p * 32 + c4];
    float* dst = &g_A[(size_t)cell * CIN + c4 * 4];
    atomicAdd(dst + 0, v.x);
    atomicAdd(dst + 1, v.y);
    atomicAdd(dst + 2, v.z);
    atomicAdd(dst + 3, v.w);
    if (c4 == 0) atomicAdd(&g_occ[cell], 1);
}

// ---------------- K1b: fp32 grid -> bf16 hi/lo swizzled slab images ----------------
__global__ void k_convert() {
    int i = blockIdx.x * 256 + threadIdx.x;        // NCELL*16 chunks
    int slab   = i >> 11;                          // 2048 chunks per slab
    int within = i & 2047;
    int cell = within >> 4, c16 = within & 15;
    const float4* p = (const float4*)(g_A + ((size_t)slab * 128 + cell) * CIN + c16 * 8);
    float4 v0 = p[0], v1 = p[1];
    float xs[8] = {v0.x, v0.y, v0.z, v0.w, v1.x, v1.y, v1.z, v1.w};
    uint32_t hi4[4], lo4[4];
#pragma unroll
    for (int j = 0; j < 4; j++) {
        __nv_bfloat16 h0 = __float2bfloat16_rn(xs[2*j]);
        __nv_bfloat16 h1 = __float2bfloat16_rn(xs[2*j+1]);
        __nv_bfloat16 l0 = __float2bfloat16_rn(xs[2*j]   - __bfloat162float(h0));
        __nv_bfloat16 l1 = __float2bfloat16_rn(xs[2*j+1] - __bfloat162float(h1));
        hi4[j] = ((uint32_t)__bfloat16_as_ushort(h1) << 16) | __bfloat16_as_ushort(h0);
        lo4[j] = ((uint32_t)__bfloat16_as_ushort(l1) << 16) | __bfloat16_as_ushort(l0);
    }
    uint32_t off = (uint32_t)(cell * 256) + chunk_off(c16, cell & 7);
    unsigned char* base = g_Ab + (size_t)slab * 65536;
    *(uint4*)(base + off)         = make_uint4(hi4[0], hi4[1], hi4[2], hi4[3]);
    *(uint4*)(base + 32768 + off) = make_uint4(lo4[0], lo4[1], lo4[2], lo4[3]);
}

// ---------------- K2: pipelined mma.sync gather transposed conv ----------------
// smem: A buf0 [0,64K), A buf1 [64K,128K)  (each: hi 32K + lo 32K)
//       W at 128K..224K: [kx(0..2)][hi 16K][lo 16K]
#define SM_W 131072
#define CONV_DYN_SMEM (131072 + 98304)

__global__ void __launch_bounds__(512, 1) k_conv(float* __restrict__ out) {
    extern __shared__ char smem[];
    const uint32_t sb = smem_u32(smem);
    const int tid = threadIdx.x, wid = tid >> 5, lane = tid & 31;
    const int half = wid >> 3, wm = wid & 7;

    const int bid = blockIdx.x;
    const int oy = bid % YOQ;
    const int bt = bid / YOQ;
    const int b = bt >> 3, ot = bt & 7;

    // y taps
    int nky, cys[2], kys[2];
    if ((oy & 1) == 0) { nky = 1; cys[0] = oy >> 1;       kys[0] = 1; }
    else               { nky = 2; cys[0] = (oy + 1) >> 1; kys[0] = 0;
                                  cys[1] = (oy - 1) >> 1; kys[1] = 2; }

    // iteration list
    int nIter = 0, slabI[6], koffI[6];
    for (int kt = 0; kt < 3; kt++) {
        int ctv = ot + 1 - kt;
        if (ctv < 0 || ctv >= TQ) continue;
        for (int yt = 0; yt < nky; yt++) {
            slabI[nIter] = (b * TQ + ctv) * YQ + cys[yt];
            koffI[nIter] = (kt * 3 + kys[yt]) * 3;
            nIter++;
        }
    }

    // ldmatrix geometry
    const int r0 = wm << 4;
    const int matL = lane >> 3, rr = lane & 7;
    const int rA0 = r0 + rr + ((matL & 1) << 3);
    const int rA1 = rA0 + 1;                 // kx=0 shifted row (row 128 garbage, masked)
    const int cA  = matL >> 1;
    const uint32_t baseA0 = (uint32_t)rA0 * 256; const int rs0 = rA0 & 7;
    const uint32_t baseA1 = (uint32_t)rA1 * 256; const int rs1 = rA1 & 7;
    const int nrB = half * 32 + rr + ((matL >> 1) << 3);
    const int cB  = matL & 1;
    const uint32_t baseB = (uint32_t)nrB * 256; const int rsB = nrB & 7;

    float accE[4][4], accO[4][4];
#pragma unroll
    for (int i = 0; i < 4; i++)
#pragma unroll
        for (int j = 0; j < 4; j++) { accE[i][j] = 0.f; accO[i][j] = 0.f; }

    // prefetch A[0]
    {
        const unsigned char* g = g_Ab + (size_t)slabI[0] * 65536;
#pragma unroll
        for (int j = 0; j < 8; j++) {
            int e = tid + j * 512;
            CPASYNC16(sb + e * 16, g + (size_t)e * 16);
        }
        CPCOMMIT();
    }

    for (int i = 0; i < nIter; i++) {
        const uint32_t Abuf = sb + (uint32_t)(i & 1) * 65536;
        __syncthreads();                    // prior compute done: W + other A buf free
        {   // W[i]: contiguous 96KB (kx 0..2, hi+lo each)
            const unsigned char* g = g_Wt + (size_t)koffI[i] * 32768;
#pragma unroll
            for (int j = 0; j < 12; j++) {
                int e = tid + j * 512;
                CPASYNC16(sb + SM_W + e * 16, g + (size_t)e * 16);
            }
            CPCOMMIT();
        }
        if (i + 1 < nIter) {                // prefetch A[i+1]
            const unsigned char* g = g_Ab + (size_t)slabI[i + 1] * 65536;
            uint32_t dst = sb + (uint32_t)((i + 1) & 1) * 65536;
#pragma unroll
            for (int j = 0; j < 8; j++) {
                int e = tid + j * 512;
                CPASYNC16(dst + e * 16, g + (size_t)e * 16);
            }
            CPCOMMIT();
            CPWAIT1();                      // A[i] + W[i] done; A[i+1] in flight
        } else {
            CPWAIT0();
        }
        __syncthreads();

#pragma unroll
        for (int pass = 0; pass < 3; pass++) {
            const uint32_t Ab = Abuf + ((pass == 2) ? 32768u : 0u);
            const uint32_t wp = (pass == 1) ? 16384u : 0u;
            const uint32_t W0 = sb + SM_W + 0 * 32768 + wp;
            const uint32_t W1 = sb + SM_W + 1 * 32768 + wp;
            const uint32_t W2 = sb + SM_W + 2 * 32768 + wp;
#pragma unroll
            for (int s = 0; s < 8; s++) {
                int c16a = 2 * s + cA;
                int c16b = 2 * s + cB;
                uint32_t offA0 = chunk_off(c16a, rs0);
                uint32_t offA1 = chunk_off(c16a, rs1);
                uint32_t offB  = chunk_off(c16b, rsB);
                uint32_t a0[4], a1[4];
                ldsm4(a0, Ab + baseA0 + offA0);
                ldsm4(a1, Ab + baseA1 + offA1);
                uint32_t b0f[8], b1f[8], b2f[8];
#pragma unroll
                for (int p2 = 0; p2 < 2; p2++) {
                    uint32_t ro = baseB + (uint32_t)(p2 * 4096) + offB;
                    ldsm4(&b1f[4 * p2], W1 + ro);
                    ldsm4(&b2f[4 * p2], W2 + ro);
                    ldsm4(&b0f[4 * p2], W0 + ro);
                }
#pragma unroll
                for (int nt = 0; nt < 4; nt++) {
                    int i2 = ((nt >> 1) << 2) + ((nt & 1) << 1);
                    mma16816(accE[nt], a0, b1f[i2], b1f[i2 + 1]);  // even: kx=1, cell m
                    mma16816(accO[nt], a0, b2f[i2], b2f[i2 + 1]);  // odd:  kx=2, cell m
                    mma16816(accO[nt], a1, b0f[i2], b0f[i2 + 1]);  // odd:  kx=0, cell m+1
                }
            }
        }
    }

    // ---------------- epilogue: stores + stats ----------------
    const int g = lane >> 2;
    const int n0base = (lane & 3) * 2;
    const int sbase = ((b * TQ + ot) * YOQ + oy) * XOQ;
    const int mA = r0 + g;
    const int mB = r0 + g + 8;
    const bool oddBvalid = (mB != 127);          // ox=255 doesn't exist

    float sl[8], ql[8];
#pragma unroll
    for (int nt = 0; nt < 4; nt++) {
        int n0 = half * 32 + nt * 8 + n0base;
        *(float2*)(out + (size_t)(sbase + 2 * mA) * COUTQ + n0) =
            make_float2(accE[nt][0], accE[nt][1]);
        *(float2*)(out + (size_t)(sbase + 2 * mB) * COUTQ + n0) =
            make_float2(accE[nt][2], accE[nt][3]);
        *(float2*)(out + (size_t)(sbase + 2 * mA + 1) * COUTQ + n0) =
            make_float2(accO[nt][0], accO[nt][1]);
        if (oddBvalid)
            *(float2*)(out + (size_t)(sbase + 2 * mB + 1) * COUTQ + n0) =
                make_float2(accO[nt][2], accO[nt][3]);
#pragma unroll
        for (int c = 0; c < 2; c++) {
            float e0 = accE[nt][c], e2 = accE[nt][2 + c];
            float o0 = accO[nt][c], o2 = oddBvalid ? accO[nt][2 + c] : 0.f;
            sl[nt * 2 + c] = e0 + e2 + o0 + o2;
            ql[nt * 2 + c] = e0 * e0 + e2 * e2 + o0 * o0 + o2 * o2;
        }
    }
#pragma unroll
    for (int d = 4; d <= 16; d <<= 1) {
#pragma unroll
        for (int i = 0; i < 8; i++) {
            sl[i] += __shfl_xor_sync(0xffffffffu, sl[i], d);
            ql[i] += __shfl_xor_sync(0xffffffffu, ql[i], d);
        }
    }
    __syncthreads();                          // reuse W smem for reduce
    float* redS = (float*)(smem + SM_W);              // [16 warps][4][8]
    float* redQ = (float*)(smem + SM_W + 16 * 4 * 8 * 4);
    if (lane < 4) {
#pragma unroll
        for (int i = 0; i < 8; i++) {
            redS[(wid * 4 + lane) * 8 + i] = sl[i];
            redQ[(wid * 4 + lane) * 8 + i] = ql[i];
        }
    }
    __syncthreads();
    if (tid < COUTQ) {
        // cout = half*32 + nt*8 + c4*2 + cc
        int h2 = tid >> 5, nt = (tid >> 3) & 3, c4 = (tid >> 1) & 3, cc = tid & 1;
        int idx = nt * 2 + cc;
        float S = 0.f, Q = 0.f;
#pragma unroll
        for (int w2 = 0; w2 < 8; w2++) {
            int w = h2 * 8 + w2;
            S += redS[(w * 4 + c4) * 8 + idx];
            Q += redQ[(w * 4 + c4) * 8 + idx];
        }
        atomicAdd(&g_sum[tid], S);
        atomicAdd(&g_sumsq[tid], Q);
    }

    // ---------------- active-site mask ----------------
    bool act = false;
    if (tid < XOQ) {
        int ox2 = tid;
        int xc[2]; int nxc = 0;
        if ((ox2 & 1) == 0) { xc[nxc++] = ox2 >> 1; }
        else {
            int c0 = (ox2 + 1) >> 1;
            if (c0 < XQ) xc[nxc++] = c0;
            xc[nxc++] = (ox2 - 1) >> 1;
        }
        for (int kt = 0; kt < 3 && !act; kt++) {
            int ctv = ot + 1 - kt;
            if (ctv < 0 || ctv >= TQ) continue;
            for (int yt = 0; yt < nky && !act; yt++) {
                int cb2 = ((b * TQ + ctv) * YQ + cys[yt]) * XQ;
                for (int xi = 0; xi < nxc; xi++)
                    if (g_occ[cb2 + xc[xi]] > 0) { act = true; break; }
            }
        }
        g_mask[sbase + ox2] = act ? 1 : 0;
    }
    unsigned bal = __ballot_sync(0xffffffffu, act);
    if (lane == 0 && bal) atomicAdd(&g_nactive, __popc(bal));
}

// ---------------- K3: fold BN params ----------------
__global__ void k_bn(const float* __restrict__ gamma, const float* __restrict__ beta) {
    int c = threadIdx.x;
    if (c >= COUTQ) return;
    float n = (float)max(g_nactive, 1);
    float mean = g_sum[c] / n;
    float var  = g_sumsq[c] / n - mean * mean;
    float rstd = rsqrtf(var + EPSQ);
    float sc   = rstd * gamma[c];
    g_scale[c] = sc;
    g_shift[c] = beta[c] - mean * sc;
}

// ---------------- K4: normalize + relu + mask (in place) ----------------
__global__ void k_final(float* __restrict__ out) {
    int i = blockIdx.x * 256 + threadIdx.x;
    int site = i >> 4;
    int cg   = i & 15;
    float4 v  = ((float4*)out)[i];
    float4 sc = ((const float4*)g_scale)[cg];
    float4 sh = ((const float4*)g_shift)[cg];
    float  m  = g_mask[site] ? 1.f : 0.f;
    v.x = fmaxf(v.x * sc.x + sh.x, 0.f) * m;
    v.y = fmaxf(v.y * sc.y + sh.y, 0.f) * m;
    v.z = fmaxf(v.z * sc.z + sh.z, 0.f) * m;
    v.w = fmaxf(v.w * sc.w + sh.w, 0.f) * m;
    ((float4*)out)[i] = v;
}

// ---------------- launch ----------------
extern "C" void kernel_launch(void* const* d_in, const int* in_sizes, int n_in,
                              void* d_out, int out_size) {
    const float* feats  = (const float*)d_in[0];
    const float* weight = (const float*)d_in[1];
    const float* gamma  = (const float*)d_in[2];
    const float* beta   = (const float*)d_in[3];
    const int*   cb     = (const int*)d_in[4];
    const int*   ct     = (const int*)d_in[5];
    const int*   cy     = (const int*)d_in[6];
    const int*   cx     = (const int*)d_in[7];
    float* out = (float*)d_out;

    cudaFuncSetAttribute(k_conv, cudaFuncAttributeMaxDynamicSharedMemorySize, CONV_DYN_SMEM);

    k_zero<<<NCELL * CIN / 4 / 256, 256>>>();
    k_prepw<<<(27 * CIN * COUTQ + 255) / 256, 256>>>(weight);
    k_scatter<<<NPTS * 32 / 256, 256>>>(feats, cb, ct, cy, cx);
    k_convert<<<NCELL * 16 / 256, 256>>>();
    k_conv<<<BQ * TQ * YOQ, 512, CONV_DYN_SMEM>>>(out);
    k_bn<<<1, 64>>>(gamma, beta);
    k_final<<<NSITE * 16 / 256, 256>>>(out);
}

// round 6
// speedup vs baseline: 4.3567x; 1.9450x over previous
#include <cuda_runtime.h>
#include <cuda_bf16.h>
#include <cstdint>

// ---------------- problem constants ----------------
#define BQ 2
#define TQ 8
#define YQ 128
#define XQ 128
#define CIN 128
#define COUTQ 64
#define YOQ 255
#define XOQ 255
#define NPTS 262144
#define NCELL (BQ*TQ*YQ*XQ)
#define NSITE (BQ*TQ*YOQ*XOQ)
#define EPSQ 1e-5f

// ---------------- device scratch ----------------
__device__ __align__(16) float g_A[(size_t)NCELL * CIN];   // fp32 cell grid (tf32-rounded in place)
__device__ __align__(16) int   g_occ[NCELL];
__device__ unsigned char       g_mask[NSITE];
__device__ __align__(16) float g_sum[COUTQ];
__device__ __align__(16) float g_sumsq[COUTQ];
__device__ int                 g_nactive;
__device__ __align__(16) float g_scale[COUTQ];
__device__ __align__(16) float g_shift[COUTQ];
// tf32(fp32-bits) swizzled weight images: [27 koff][64 co x 512B]
__device__ __align__(16) uint32_t g_Wt32[27 * 8192];

// ---------------- helpers ----------------
__device__ __forceinline__ uint32_t smem_u32(const void* p) {
    uint32_t a;
    asm("{ .reg .u64 t; cvta.to.shared.u64 t, %1; cvt.u32.u64 %0, t; }" : "=r"(a) : "l"(p));
    return a;
}
__device__ __forceinline__ void ldsm4(uint32_t* r, uint32_t addr) {
    asm volatile("ldmatrix.sync.aligned.m8n8.x4.shared.b16 {%0,%1,%2,%3}, [%4];"
        : "=r"(r[0]), "=r"(r[1]), "=r"(r[2]), "=r"(r[3]) : "r"(addr));
}
__device__ __forceinline__ void mma_tf32(float* c, const uint32_t* a, uint32_t b0, uint32_t b1) {
    asm volatile("mma.sync.aligned.m16n8k8.row.col.f32.tf32.tf32.f32 "
        "{%0,%1,%2,%3}, {%4,%5,%6,%7}, {%8,%9}, {%0,%1,%2,%3};"
        : "+f"(c[0]), "+f"(c[1]), "+f"(c[2]), "+f"(c[3])
        : "r"(a[0]), "r"(a[1]), "r"(a[2]), "r"(a[3]), "r"(b0), "r"(b1));
}
__device__ __forceinline__ uint32_t f2tf32(float x) {
    uint32_t t;
    asm("cvt.rna.tf32.f32 %0, %1;" : "=r"(t) : "f"(x));
    return t;
}
#define CPASYNC16(sa, gp) \
    asm volatile("cp.async.cg.shared.global [%0], [%1], 16;" :: "r"(sa), "l"(gp))
#define CPCOMMIT() asm volatile("cp.async.commit_group;" ::: "memory")
#define CPWAIT(n)  asm volatile("cp.async.wait_group %0;" :: "n"(n) : "memory")

// 512B rows of 32 16B-chunks, XOR-swizzled within 8-chunk groups.
__device__ __forceinline__ uint32_t chunk_off32(int c, int rs) {
    return (uint32_t)(((c & 24) | ((c & 7) ^ rs)) << 4);
}

// ---------------- K0: zero scratch ----------------
__global__ void k_zero() {
    int idx = blockIdx.x * 256 + threadIdx.x;
    if (idx < NCELL * CIN / 4)
        ((float4*)g_A)[idx] = make_float4(0.f, 0.f, 0.f, 0.f);
    if (idx < NCELL / 4)
        ((int4*)g_occ)[idx] = make_int4(0, 0, 0, 0);
    if (idx < COUTQ) { g_sum[idx] = 0.f; g_sumsq[idx] = 0.f; }
    if (idx == 0) g_nactive = 0;
}

// ---------------- K0b: tf32-round + swizzle weights ----------------
// src [koff][ci][co] -> image: row=co (512B = 128 ci words), swizzled chunks
__global__ void k_prepw(const float* __restrict__ W) {
    int i = blockIdx.x * 256 + threadIdx.x;
    if (i >= 27 * CIN * COUTQ) return;
    int koff = i / (CIN * COUTQ);
    int r    = i % (CIN * COUTQ);
    int ci = r / COUTQ, co = r % COUTQ;
    uint32_t t = f2tf32(W[i]);
    uint32_t off = (uint32_t)(co * 512) + chunk_off32(ci >> 2, co & 7) + (ci & 3) * 4;
    *(uint32_t*)((char*)g_Wt32 + (size_t)koff * 32768 + off) = t;
}

// ---------------- K1: scatter points ----------------
__global__ void k_scatter(const float* __restrict__ feats,
                          const int* __restrict__ cb, const int* __restrict__ ct,
                          const int* __restrict__ cy, const int* __restrict__ cx) {
    int i = blockIdx.x * 256 + threadIdx.x;
    if (i >= NPTS * 32) return;
    int p  = i >> 5;
    int c4 = i & 31;
    int cell = ((cb[p] * TQ + ct[p]) * YQ + cy[p]) * XQ + cx[p];
    float4 v = ((const float4*)feats)[p * 32 + c4];
    float* dst = &g_A[(size_t)cell * CIN + c4 * 4];
    atomicAdd(dst + 0, v.x);
    atomicAdd(dst + 1, v.y);
    atomicAdd(dst + 2, v.z);
    atomicAdd(dst + 3, v.w);
    if (c4 == 0) atomicAdd(&g_occ[cell], 1);
}

// ---------------- K1b: tf32-round g_A in place ----------------
__global__ void k_convert() {
    int i = blockIdx.x * 256 + threadIdx.x;        // NCELL*CIN/4
    float4 v = ((const float4*)g_A)[i];
    v.x = __uint_as_float(f2tf32(v.x));
    v.y = __uint_as_float(f2tf32(v.y));
    v.z = __uint_as_float(f2tf32(v.z));
    v.w = __uint_as_float(f2tf32(v.w));
    ((float4*)g_A)[i] = v;
}

// ---------------- K2: pipelined tf32 mma gather transposed conv ----------------
// smem: A buf0 [0,64K), A buf1 [64K,128K)  (fp32, rows=cell 512B, swizzled)
//       W at 128K: kx1 [0,32K), kx2 [32K,64K), kx0 [64K,96K)
#define SM_W 131072
#define CONV_DYN_SMEM (131072 + 98304)

__global__ void __launch_bounds__(512, 1) k_conv(float* __restrict__ out) {
    extern __shared__ char smem[];
    const uint32_t sb = smem_u32(smem);
    const int tid = threadIdx.x, wid = tid >> 5, lane = tid & 31;
    const int half = wid >> 3, wm = wid & 7;

    const int bid = blockIdx.x;
    const int oy = bid % YOQ;
    const int bt = bid / YOQ;
    const int b = bt >> 3, ot = bt & 7;

    // y taps
    int nky, cys[2], kys[2];
    if ((oy & 1) == 0) { nky = 1; cys[0] = oy >> 1;       kys[0] = 1; }
    else               { nky = 2; cys[0] = (oy + 1) >> 1; kys[0] = 0;
                                  cys[1] = (oy - 1) >> 1; kys[1] = 2; }

    // iteration list
    int nIter = 0, slabI[6], koffI[6];
    for (int kt = 0; kt < 3; kt++) {
        int ctv = ot + 1 - kt;
        if (ctv < 0 || ctv >= TQ) continue;
        for (int yt = 0; yt < nky; yt++) {
            slabI[nIter] = (b * TQ + ctv) * YQ + cys[yt];
            koffI[nIter] = (kt * 3 + kys[yt]) * 3;
            nIter++;
        }
    }

    // ldmatrix geometry (tf32 frags via b16 ldmatrix on 8x4-fp32 tiles)
    const int r0 = wm << 4;
    const int matL = lane >> 3, rr = lane & 7;
    const int rA0 = r0 + rr + ((matL & 1) << 3);
    const int rA1 = rA0 + 1;                  // kx=0 shifted row (row 128 garbage, masked)
    const int cSel = matL >> 1;               // chunk select (k halves)
    const uint32_t baseA0 = (uint32_t)rA0 * 512; const int rs0 = rA0 & 7;
    const uint32_t baseA1 = (uint32_t)rA1 * 512; const int rs1 = rA1 & 7;
    const int rowB = half * 32 + rr + ((matL & 1) << 3);
    const uint32_t baseB0 = (uint32_t)rowB * 512;
    const uint32_t baseB1 = baseB0 + 16 * 512;
    const int rsB = rowB & 7;                 // +16 rows keeps (row&7)

    float accE[4][4], accO[4][4];
#pragma unroll
    for (int i = 0; i < 4; i++)
#pragma unroll
        for (int j = 0; j < 4; j++) { accE[i][j] = 0.f; accO[i][j] = 0.f; }

    // prefetch A[0] into buf0
    {
        const char* g = (const char*)g_A + (size_t)slabI[0] * 65536;
#pragma unroll
        for (int j = 0; j < 8; j++) {
            int e = tid + j * 512;
            int cell = e >> 5, c16 = e & 31;
            CPASYNC16(sb + cell * 512 + chunk_off32(c16, cell & 7), g + (size_t)e * 16);
        }
        CPCOMMIT();
    }

    for (int i = 0; i < nIter; i++) {
        const uint32_t Abuf = sb + (uint32_t)(i & 1) * 65536;
        __syncthreads();                       // prior readers of W + other A buf done
        {   // group 1: W[kx1], W[kx2] (contiguous 64KB)
            const char* g = (const char*)g_Wt32 + ((size_t)koffI[i] + 1) * 32768;
#pragma unroll
            for (int j = 0; j < 8; j++) {
                int e = tid + j * 512;
                CPASYNC16(sb + SM_W + e * 16, g + (size_t)e * 16);
            }
            CPCOMMIT();
        }
        {   // group 2: W[kx0] (32KB)
            const char* g = (const char*)g_Wt32 + (size_t)koffI[i] * 32768;
#pragma unroll
            for (int j = 0; j < 4; j++) {
                int e = tid + j * 512;
                CPASYNC16(sb + SM_W + 65536 + e * 16, g + (size_t)e * 16);
            }
            CPCOMMIT();
        }
        {   // group 3: A[i+1] prefetch (dummy refetch of slab0 on last iter)
            int ns = (i + 1 < nIter) ? slabI[i + 1] : slabI[0];
            const char* g = (const char*)g_A + (size_t)ns * 65536;
            uint32_t dst = sb + (uint32_t)((i + 1) & 1) * 65536;
#pragma unroll
            for (int j = 0; j < 8; j++) {
                int e = tid + j * 512;
                int cell = e >> 5, c16 = e & 31;
                CPASYNC16(dst + cell * 512 + chunk_off32(c16, cell & 7), g + (size_t)e * 16);
            }
            CPCOMMIT();
        }
        CPWAIT(2);            // A[i] + W[kx1,kx2] complete
        __syncthreads();

        // ---- phase 1: even (kx=1) + odd (kx=2), A rows m ----
#pragma unroll
        for (int s = 0; s < 16; s++) {
            uint32_t offA = chunk_off32(2 * s + cSel, rs0);
            uint32_t offB = chunk_off32(2 * s + cSel, rsB);
            uint32_t a0[4];
            ldsm4(a0, Abuf + baseA0 + offA);
#pragma unroll
            for (int j2 = 0; j2 < 2; j2++) {
                uint32_t bb = (j2 ? baseB1 : baseB0) + offB;
                uint32_t b1v[4], b2v[4];
                ldsm4(b1v, sb + SM_W + bb);
                ldsm4(b2v, sb + SM_W + 32768 + bb);
                mma_tf32(accE[2 * j2],     a0, b1v[0], b1v[2]);
                mma_tf32(accE[2 * j2 + 1], a0, b1v[1], b1v[3]);
                mma_tf32(accO[2 * j2],     a0, b2v[0], b2v[2]);
                mma_tf32(accO[2 * j2 + 1], a0, b2v[1], b2v[3]);
            }
        }
        CPWAIT(1);            // W[kx0] complete
        __syncthreads();

        // ---- phase 2: odd (kx=0), A rows m+1 ----
#pragma unroll
        for (int s = 0; s < 16; s++) {
            uint32_t offA = chunk_off32(2 * s + cSel, rs1);
            uint32_t offB = chunk_off32(2 * s + cSel, rsB);
            uint32_t a1v[4];
            ldsm4(a1v, Abuf + baseA1 + offA);
#pragma unroll
            for (int j2 = 0; j2 < 2; j2++) {
                uint32_t bb = (j2 ? baseB1 : baseB0) + offB;
                uint32_t b0v[4];
                ldsm4(b0v, sb + SM_W + 65536 + bb);
                mma_tf32(accO[2 * j2],     a1v, b0v[0], b0v[2]);
                mma_tf32(accO[2 * j2 + 1], a1v, b0v[1], b0v[3]);
            }
        }
    }
    CPWAIT(0);                 // drain dummy A prefetch before smem reuse

    // ---------------- epilogue: stores + stats ----------------
    const int g = lane >> 2;
    const int n0base = (lane & 3) * 2;
    const int sbase = ((b * TQ + ot) * YOQ + oy) * XOQ;
    const int mA = r0 + g;
    const int mB = r0 + g + 8;
    const bool oddBvalid = (mB != 127);          // ox=255 doesn't exist

    float sl[8], ql[8];
#pragma unroll
    for (int nt = 0; nt < 4; nt++) {
        int n0 = half * 32 + nt * 8 + n0base;
        *(float2*)(out + (size_t)(sbase + 2 * mA) * COUTQ + n0) =
            make_float2(accE[nt][0], accE[nt][1]);
        *(float2*)(out + (size_t)(sbase + 2 * mB) * COUTQ + n0) =
            make_float2(accE[nt][2], accE[nt][3]);
        *(float2*)(out + (size_t)(sbase + 2 * mA + 1) * COUTQ + n0) =
            make_float2(accO[nt][0], accO[nt][1]);
        if (oddBvalid)
            *(float2*)(out + (size_t)(sbase + 2 * mB + 1) * COUTQ + n0) =
                make_float2(accO[nt][2], accO[nt][3]);
#pragma unroll
        for (int c = 0; c < 2; c++) {
            float e0 = accE[nt][c], e2 = accE[nt][2 + c];
            float o0 = accO[nt][c], o2 = oddBvalid ? accO[nt][2 + c] : 0.f;
            sl[nt * 2 + c] = e0 + e2 + o0 + o2;
            ql[nt * 2 + c] = e0 * e0 + e2 * e2 + o0 * o0 + o2 * o2;
        }
    }
#pragma unroll
    for (int d = 4; d <= 16; d <<= 1) {
#pragma unroll
        for (int i = 0; i < 8; i++) {
            sl[i] += __shfl_xor_sync(0xffffffffu, sl[i], d);
            ql[i] += __shfl_xor_sync(0xffffffffu, ql[i], d);
        }
    }
    __syncthreads();                          // reuse W smem for reduce
    float* redS = (float*)(smem + SM_W);              // [16 warps][4][8]
    float* redQ = (float*)(smem + SM_W + 16 * 4 * 8 * 4);
    if (lane < 4) {
#pragma unroll
        for (int i = 0; i < 8; i++) {
            redS[(wid * 4 + lane) * 8 + i] = sl[i];
            redQ[(wid * 4 + lane) * 8 + i] = ql[i];
        }
    }
    __syncthreads();
    if (tid < COUTQ) {
        // cout = half*32 + nt*8 + c4*2 + cc
        int h2 = tid >> 5, nt = (tid >> 3) & 3, c4 = (tid >> 1) & 3, cc = tid & 1;
        int idx = nt * 2 + cc;
        float S = 0.f, Q = 0.f;
#pragma unroll
        for (int w2 = 0; w2 < 8; w2++) {
            int w = h2 * 8 + w2;
            S += redS[(w * 4 + c4) * 8 + idx];
            Q += redQ[(w * 4 + c4) * 8 + idx];
        }
        atomicAdd(&g_sum[tid], S);
        atomicAdd(&g_sumsq[tid], Q);
    }

    // ---------------- active-site mask ----------------
    bool act = false;
    if (tid < XOQ) {
        int ox2 = tid;
        int xc[2]; int nxc = 0;
        if ((ox2 & 1) == 0) { xc[nxc++] = ox2 >> 1; }
        else {
            int c0 = (ox2 + 1) >> 1;
            if (c0 < XQ) xc[nxc++] = c0;
            xc[nxc++] = (ox2 - 1) >> 1;
        }
        for (int kt = 0; kt < 3 && !act; kt++) {
            int ctv = ot + 1 - kt;
            if (ctv < 0 || ctv >= TQ) continue;
            for (int yt = 0; yt < nky && !act; yt++) {
                int cb2 = ((b * TQ + ctv) * YQ + cys[yt]) * XQ;
                for (int xi = 0; xi < nxc; xi++)
                    if (g_occ[cb2 + xc[xi]] > 0) { act = true; break; }
            }
        }
        g_mask[sbase + ox2] = act ? 1 : 0;
    }
    unsigned bal = __ballot_sync(0xffffffffu, act);
    if (lane == 0 && bal) atomicAdd(&g_nactive, __popc(bal));
}

// ---------------- K3: fold BN params ----------------
__global__ void k_bn(const float* __restrict__ gamma, const float* __restrict__ beta) {
    int c = threadIdx.x;
    if (c >= COUTQ) return;
    float n = (float)max(g_nactive, 1);
    float mean = g_sum[c] / n;
    float var  = g_sumsq[c] / n - mean * mean;
    float rstd = rsqrtf(var + EPSQ);
    float sc   = rstd * gamma[c];
    g_scale[c] = sc;
    g_shift[c] = beta[c] - mean * sc;
}

// ---------------- K4: normalize + relu + mask (in place) ----------------
__global__ void k_final(float* __restrict__ out) {
    int i = blockIdx.x * 256 + threadIdx.x;
    int site = i >> 4;
    int cg   = i & 15;
    float4 v  = ((float4*)out)[i];
    float4 sc = ((const float4*)g_scale)[cg];
    float4 sh = ((const float4*)g_shift)[cg];
    float  m  = g_mask[site] ? 1.f : 0.f;
    v.x = fmaxf(v.x * sc.x + sh.x, 0.f) * m;
    v.y = fmaxf(v.y * sc.y + sh.y, 0.f) * m;
    v.z = fmaxf(v.z * sc.z + sh.z, 0.f) * m;
    v.w = fmaxf(v.w * sc.w + sh.w, 0.f) * m;
    ((float4*)out)[i] = v;
}

// ---------------- launch ----------------
extern "C" void kernel_launch(void* const* d_in, const int* in_sizes, int n_in,
                              void* d_out, int out_size) {
    const float* feats  = (const float*)d_in[0];
    const float* weight = (const float*)d_in[1];
    const float* gamma  = (const float*)d_in[2];
    const float* beta   = (const float*)d_in[3];
    const int*   cb     = (const int*)d_in[4];
    const int*   ct     = (const int*)d_in[5];
    const int*   cy     = (const int*)d_in[6];
    const int*   cx     = (const int*)d_in[7];
    float* out = (float*)d_out;

    cudaFuncSetAttribute(k_conv, cudaFuncAttributeMaxDynamicSharedMemorySize, CONV_DYN_SMEM);

    k_zero<<<NCELL * CIN / 4 / 256, 256>>>();
    k_prepw<<<(27 * CIN * COUTQ + 255) / 256, 256>>>(weight);
    k_scatter<<<NPTS * 32 / 256, 256>>>(feats, cb, ct, cy, cx);
    k_convert<<<NCELL * CIN / 4 / 256, 256>>>();
    k_conv<<<BQ * TQ * YOQ, 512, CONV_DYN_SMEM>>>(out);
    k_bn<<<1, 64>>>(gamma, beta);
    k_final<<<NSITE * 16 / 256, 256>>>(out);
}